// round 7
// baseline (speedup 1.0000x reference)
#include <cuda_runtime.h>
#include <cstdint>

// Problem shapes (fixed by the reference)
#define B_  8
#define T_  512
#define H_  8
#define D_  128
#define S_  8192

// N = elements per cache tensor = B*S*H*D = 67,108,864 floats
#define N_ELEM   (B_ * S_ * H_ * D_)

// ---------------------------------------------------------------------------
// Kernel 1: bulk copy cache_k -> out[0..N), cache_v -> out[N..2N)
// Pure streaming: float4, ld.global.cs / st.global.cs (no reuse).
// ---------------------------------------------------------------------------
__global__ void __launch_bounds__(256) copy_caches_kernel(
    const float4* __restrict__ cache_k,
    const float4* __restrict__ cache_v,
    float4* __restrict__ out)
{
    const long long n4 = N_ELEM / 4;          // float4 per tensor
    const long long i = (long long)blockIdx.x * blockDim.x + threadIdx.x;
    const long long stride = (long long)gridDim.x * blockDim.x;

    // First half: K
    for (long long j = i; j < n4; j += stride) {
        float4 v = __ldcs(&cache_k[j]);
        __stcs(&out[j], v);
    }
    // Second half: V
    float4* outv = out + n4;
    for (long long j = i; j < n4; j += stride) {
        float4 v = __ldcs(&cache_v[j]);
        __stcs(&outv[j], v);
    }
}

// ---------------------------------------------------------------------------
// Kernel 2: scatter RoPE(k_new) and v_new into the output at `positions`.
// One thread per float4 of k_new (= 2 interleaved rope pairs) + matching
// v_new float4.
// Thread index decomposition: [b(3b) | t(9b) | h(3b) | d4(5b)]  (D/4 = 32)
// ---------------------------------------------------------------------------
__global__ void __launch_bounds__(256) scatter_update_kernel(
    const float4* __restrict__ k_new,        // (B,T,H,D) as float4
    const float4* __restrict__ v_new,
    const float2* __restrict__ cos_t,        // (S, D/2) as float2 pairs
    const float2* __restrict__ sin_t,
    const int*    __restrict__ positions,    // (B,T) int32 (JAX x64 disabled)
    float4* __restrict__ out)                // (2,B,S,H,D)
{
    const int idx = blockIdx.x * blockDim.x + threadIdx.x;
    const int d4 = idx & 31;            // 0..31  (float4 index within D)
    const int h  = (idx >> 5) & 7;
    const int t  = (idx >> 8) & 511;
    const int b  = idx >> 17;

    const int p = positions[b * T_ + t];   // 0..B*T-1 < S

    // source offset in (B,T,H,D)/4
    const long long src4 = ((((long long)b * T_ + t) * H_ + h) * (D_ / 4)) + d4;
    // dest offset in (B,S,H,D)/4
    const long long dst4 = ((((long long)b * S_ + p) * H_ + h) * (D_ / 4)) + d4;

    // RoPE for K: pairs (4*d4, 4*d4+1) and (4*d4+2, 4*d4+3)
    const float4 k = __ldcs(&k_new[src4]);
    // cos/sin: row p of (S, D/2), viewed as float2[D/4] per row
    const long long cs_off = (long long)p * (D_ / 4) + d4;
    const float2 c = __ldg(&cos_t[cs_off]);
    const float2 s = __ldg(&sin_t[cs_off]);

    float4 r;
    r.x = k.x * c.x - k.y * s.x;
    r.y = k.x * s.x + k.y * c.x;
    r.z = k.z * c.y - k.w * s.y;
    r.w = k.z * s.y + k.w * c.y;

    __stcs(&out[dst4], r);

    // V: straight copy into second half of out
    const float4 v = __ldcs(&v_new[src4]);
    __stcs(&out[(long long)(N_ELEM / 4) + dst4], v);
}

// ---------------------------------------------------------------------------
// Launch: copy, then scatter (stream order supplies overwrite semantics).
// Inputs (metadata order):
//   0: k_new (B,T,H,D) f32      1: v_new (B,T,H,D) f32
//   2: cos (S,D/2) f32          3: sin (S,D/2) f32
//   4: cache_k (B,S,H,D) f32    5: cache_v (B,S,H,D) f32
//   6: positions (B,T) int32
// ---------------------------------------------------------------------------
extern "C" void kernel_launch(void* const* d_in, const int* in_sizes, int n_in,
                              void* d_out, int out_size)
{
    const float4* k_new   = (const float4*)d_in[0];
    const float4* v_new   = (const float4*)d_in[1];
    const float2* cos_t   = (const float2*)d_in[2];
    const float2* sin_t   = (const float2*)d_in[3];
    const float4* cache_k = (const float4*)d_in[4];
    const float4* cache_v = (const float4*)d_in[5];
    const int*    pos     = (const int*)d_in[6];
    float4* out = (float4*)d_out;

    // Copy: 8192 blocks x 256 threads -> 8 float4 per thread per half.
    copy_caches_kernel<<<8192, 256>>>(cache_k, cache_v, out);

    // Scatter: exactly B*T*H*(D/4) = 1,048,576 threads
    {
        const int threads = 256;
        const int blocks = (B_ * T_ * H_ * (D_ / 4)) / threads;  // 4096
        scatter_update_kernel<<<blocks, threads>>>(k_new, v_new, cos_t, sin_t,
                                                   pos, out);
    }
}

// round 8
// speedup vs baseline: 1.0004x; 1.0004x over previous
#include <cuda_runtime.h>
#include <cstdint>

// Problem shapes (fixed by the reference)
#define B_  8
#define T_  512
#define H_  8
#define D_  128
#define S_  8192

// N = elements per cache tensor = B*S*H*D = 67,108,864 floats
#define N_ELEM   (B_ * S_ * H_ * D_)

// ---------------------------------------------------------------------------
// Kernel 1: bulk copy cache_k -> out[0..N), cache_v -> out[N..2N)
// Pure streaming: float4, ld.global.cs / st.global.cs (no reuse).
// ---------------------------------------------------------------------------
__global__ void __launch_bounds__(256) copy_caches_kernel(
    const float4* __restrict__ cache_k,
    const float4* __restrict__ cache_v,
    float4* __restrict__ out)
{
    const long long n4 = N_ELEM / 4;          // float4 per tensor
    const long long i = (long long)blockIdx.x * blockDim.x + threadIdx.x;
    const long long stride = (long long)gridDim.x * blockDim.x;

    // First half: K
    for (long long j = i; j < n4; j += stride) {
        float4 v = __ldcs(&cache_k[j]);
        __stcs(&out[j], v);
    }
    // Second half: V
    float4* outv = out + n4;
    for (long long j = i; j < n4; j += stride) {
        float4 v = __ldcs(&cache_v[j]);
        __stcs(&outv[j], v);
    }
}

// ---------------------------------------------------------------------------
// Kernel 2: scatter RoPE(k_new) and v_new into the output at `positions`.
// One thread per float4 of k_new (= 2 interleaved rope pairs) + matching
// v_new float4.
// Thread index decomposition: [b(3b) | t(9b) | h(3b) | d4(5b)]  (D/4 = 32)
// ---------------------------------------------------------------------------
__global__ void __launch_bounds__(256) scatter_update_kernel(
    const float4* __restrict__ k_new,        // (B,T,H,D) as float4
    const float4* __restrict__ v_new,
    const float2* __restrict__ cos_t,        // (S, D/2) as float2 pairs
    const float2* __restrict__ sin_t,
    const int*    __restrict__ positions,    // (B,T) int32 (JAX x64 disabled)
    float4* __restrict__ out)                // (2,B,S,H,D)
{
    const int idx = blockIdx.x * blockDim.x + threadIdx.x;
    const int d4 = idx & 31;            // 0..31  (float4 index within D)
    const int h  = (idx >> 5) & 7;
    const int t  = (idx >> 8) & 511;
    const int b  = idx >> 17;

    const int p = positions[b * T_ + t];   // 0..B*T-1 < S

    // source offset in (B,T,H,D)/4
    const long long src4 = ((((long long)b * T_ + t) * H_ + h) * (D_ / 4)) + d4;
    // dest offset in (B,S,H,D)/4
    const long long dst4 = ((((long long)b * S_ + p) * H_ + h) * (D_ / 4)) + d4;

    // RoPE for K: pairs (4*d4, 4*d4+1) and (4*d4+2, 4*d4+3)
    const float4 k = __ldcs(&k_new[src4]);
    // cos/sin: row p of (S, D/2), viewed as float2[D/4] per row
    const long long cs_off = (long long)p * (D_ / 4) + d4;
    const float2 c = __ldg(&cos_t[cs_off]);
    const float2 s = __ldg(&sin_t[cs_off]);

    float4 r;
    r.x = k.x * c.x - k.y * s.x;
    r.y = k.x * s.x + k.y * c.x;
    r.z = k.z * c.y - k.w * s.y;
    r.w = k.z * s.y + k.w * c.y;

    __stcs(&out[dst4], r);

    // V: straight copy into second half of out
    const float4 v = __ldcs(&v_new[src4]);
    __stcs(&out[(long long)(N_ELEM / 4) + dst4], v);
}

// ---------------------------------------------------------------------------
// Launch: copy, then scatter (stream order supplies overwrite semantics).
// Inputs (metadata order):
//   0: k_new (B,T,H,D) f32      1: v_new (B,T,H,D) f32
//   2: cos (S,D/2) f32          3: sin (S,D/2) f32
//   4: cache_k (B,S,H,D) f32    5: cache_v (B,S,H,D) f32
//   6: positions (B,T) int32
// ---------------------------------------------------------------------------
extern "C" void kernel_launch(void* const* d_in, const int* in_sizes, int n_in,
                              void* d_out, int out_size)
{
    const float4* k_new   = (const float4*)d_in[0];
    const float4* v_new   = (const float4*)d_in[1];
    const float2* cos_t   = (const float2*)d_in[2];
    const float2* sin_t   = (const float2*)d_in[3];
    const float4* cache_k = (const float4*)d_in[4];
    const float4* cache_v = (const float4*)d_in[5];
    const int*    pos     = (const int*)d_in[6];
    float4* out = (float4*)d_out;

    // Copy: 8192 blocks x 256 threads -> 8 float4 per thread per half.
    copy_caches_kernel<<<8192, 256>>>(cache_k, cache_v, out);

    // Scatter: exactly B*T*H*(D/4) = 1,048,576 threads
    {
        const int threads = 256;
        const int blocks = (B_ * T_ * H_ * (D_ / 4)) / threads;  // 4096
        scatter_update_kernel<<<blocks, threads>>>(k_new, v_new, cos_t, sin_t,
                                                   pos, out);
    }
}